// round 13
// baseline (speedup 1.0000x reference)
#include <cuda_runtime.h>
#include <cuda_bf16.h>
#include <cstdint>
#include <cstddef>

// ---------------------------------------------------------------------------
// LSTM T=512 B=64 I=H=512 on sm_103 (no tcgen05): mma.sync bf16 hi/lo split.
//   cvt:   x, W_ih -> bf16 hi/lo scratch
//   xproj: x_projT = W_ih @ X^T  (3-product bf16 split, ldmatrix fragment loads)
//   rec:   persistent 128-CTA recurrence; reg weights; fragment-ordered image;
//          register-direct epilogue (shfl pair publish); release/acquire barrier.
// ---------------------------------------------------------------------------

#define T_STEPS 512
#define BATCH   64
#define HID     512
#define TB      32768              // T*B
#define NROWS   2048               // 4*H gate rows

__device__ __align__(16) __nv_bfloat16 g_xhi[(size_t)TB * HID];
__device__ __align__(16) __nv_bfloat16 g_xlo[(size_t)TB * HID];
__device__ __align__(16) __nv_bfloat16 g_whi[(size_t)NROWS * HID];
__device__ __align__(16) __nv_bfloat16 g_wlo[(size_t)NROWS * HID];
__device__ __align__(16) float         g_xpT[(size_t)NROWS * TB];   // [m][tb]
// fragment-ordered h image: [parity][bh][16384 words]
__device__ __align__(16) uint32_t g_img[2][2][16384];
// per-batch-half barrier counters (128B apart to avoid line sharing)
__device__ __align__(16) unsigned long long g_bar2[32];

#define REC_NCTA 128
#define GRP_CTAS 64
#define BARS_PER_LAUNCH (511ull * GRP_CTAS)

// ------------------------------ helpers ------------------------------------
__device__ __forceinline__ unsigned long long ld_vol_u64(const unsigned long long* p) {
    unsigned long long v;
    asm volatile("ld.volatile.global.u64 %0, [%1];" : "=l"(v) : "l"(p));
    return v;
}
__device__ __forceinline__ unsigned long long ld_acq_u64(const unsigned long long* p) {
    unsigned long long v;
    asm volatile("ld.acquire.gpu.global.u64 %0, [%1];" : "=l"(v) : "l"(p));
    return v;
}
__device__ __forceinline__ void red_add_release(unsigned long long* p, unsigned long long v) {
    asm volatile("red.release.gpu.global.add.u64 [%0], %1;" :: "l"(p), "l"(v) : "memory");
}
__device__ __forceinline__ uint4 ldcg_u4(const uint32_t* p) {
    uint4 v;
    asm volatile("ld.global.cg.v4.u32 {%0,%1,%2,%3}, [%4];"
                 : "=r"(v.x), "=r"(v.y), "=r"(v.z), "=r"(v.w) : "l"(p));
    return v;
}
__device__ __forceinline__ void ldsm_x4(uint32_t (&r)[4], uint32_t saddr) {
    asm volatile("ldmatrix.sync.aligned.m8n8.x4.shared.b16 {%0,%1,%2,%3}, [%4];"
                 : "=r"(r[0]), "=r"(r[1]), "=r"(r[2]), "=r"(r[3]) : "r"(saddr));
}
__device__ __forceinline__ void mma_bf16(float (&d)[4], const uint32_t (&a)[4],
                                         const uint32_t (&b)[2]) {
    asm volatile(
        "mma.sync.aligned.m16n8k16.row.col.f32.bf16.bf16.f32 "
        "{%0,%1,%2,%3}, {%4,%5,%6,%7}, {%8,%9}, {%0,%1,%2,%3};\n"
        : "+f"(d[0]), "+f"(d[1]), "+f"(d[2]), "+f"(d[3])
        : "r"(a[0]), "r"(a[1]), "r"(a[2]), "r"(a[3]), "r"(b[0]), "r"(b[1]));
}
__device__ __forceinline__ uint32_t pack_hi2(float2 v) {
    union { __nv_bfloat162 h2; uint32_t u; } r;
    r.h2.x = __float2bfloat16(v.x);
    r.h2.y = __float2bfloat16(v.y);
    return r.u;
}
__device__ __forceinline__ uint32_t pack_lo2(float2 v) {
    union { __nv_bfloat162 h2; uint32_t u; } r;
    __nv_bfloat16 hx = __float2bfloat16(v.x);
    __nv_bfloat16 hy = __float2bfloat16(v.y);
    r.h2.x = __float2bfloat16(v.x - __bfloat162float(hx));
    r.h2.y = __float2bfloat16(v.y - __bfloat162float(hy));
    return r.u;
}
__device__ __forceinline__ float fast_sigmoid(float x) { return 1.f / (1.f + __expf(-x)); }
__device__ __forceinline__ float fast_tanh(float x) {
    float ax = fabsf(x);
    float t = 1.f - 2.f / (__expf(2.f * ax) + 1.f);
    return copysignf(t, x);
}

// ===========================================================================
// Kernel 0: fp32 -> bf16 hi/lo conversion for x and W_ih
// ===========================================================================
__global__ void cvt_kernel(const float* __restrict__ x, const float* __restrict__ W_ih) {
    const size_t stride = (size_t)gridDim.x * blockDim.x;
    const size_t gid = (size_t)blockIdx.x * blockDim.x + threadIdx.x;
    for (size_t i = gid; i < (size_t)NROWS * HID; i += stride) {
        float v = W_ih[i];
        __nv_bfloat16 h = __float2bfloat16(v);
        g_whi[i] = h;
        g_wlo[i] = __float2bfloat16(v - __bfloat162float(h));
    }
    for (size_t i = gid; i < (size_t)TB * HID; i += stride) {
        float v = x[i];
        __nv_bfloat16 h = __float2bfloat16(v);
        g_xhi[i] = h;
        g_xlo[i] = __float2bfloat16(v - __bfloat162float(h));
    }
}

// ===========================================================================
// Kernel 1: x_projT = W_ih @ X^T.  CTA tile M128 x N128, K-chunks of 64,
// cp.async double buffer. 16 warps, warp tile 32x32. 3-product split.
// Fragment loads via ldmatrix.x4. smem row: 72 elems = 144 B.
// ===========================================================================
#define KC 64
#define S1 144
#define PART1 (128 * S1)       // 18432 B per part tile
#define BUFSZ (4 * PART1)      // A_hi A_lo B_hi B_lo
#define SMEM1 (2 * BUFSZ)      // 147456 B

__device__ __forceinline__ void xp_issue(char* smc, int c, int m0, int n0, int tid) {
    const int buf = c & 1;
    const int kb = c * KC;
    char* base = smc + buf * BUFSZ;
    #pragma unroll
    for (int j = 0; j < 8; j++) {
        const int id = j * 512 + tid;
        const int which = id >> 10;        // 0 A_hi, 1 A_lo, 2 B_hi, 3 B_lo
        const int r = (id >> 3) & 127;
        const int s = id & 7;
        const __nv_bfloat16* src;
        if (which == 0)      src = g_whi + (size_t)(m0 + r) * HID + kb + s * 8;
        else if (which == 1) src = g_wlo + (size_t)(m0 + r) * HID + kb + s * 8;
        else if (which == 2) src = g_xhi + (size_t)(n0 + r) * HID + kb + s * 8;
        else                 src = g_xlo + (size_t)(n0 + r) * HID + kb + s * 8;
        const uint32_t dst =
            (uint32_t)__cvta_generic_to_shared(base + which * PART1 + r * S1 + s * 16);
        asm volatile("cp.async.cg.shared.global [%0], [%1], 16;\n" :: "r"(dst), "l"(src));
    }
    asm volatile("cp.async.commit_group;\n" ::: "memory");
}

__global__ void __launch_bounds__(512, 1) xproj_kernel() {
    extern __shared__ char smc[];
    const int tid = threadIdx.x;
    const int mt = blockIdx.x & 15, nt = blockIdx.x >> 4;
    const int m0 = mt * 128, n0 = nt * 128;
    const int warp = tid >> 5, lane = tid & 31;
    const int wm = warp >> 2, wn = warp & 3;       // 4x4 warp grid of 32x32

    const int lq = lane & 7;
    const int qa_r = ((lane >> 3) & 1) * 8;
    const int qa_c = ((lane >> 4) & 1) * 16;
    const int qb_r = ((lane >> 4) & 1) * 8;
    const int qb_c = ((lane >> 3) & 1) * 16;
    uint32_t aOff[2], bOff[2];
    #pragma unroll
    for (int mi = 0; mi < 2; mi++)
        aOff[mi] = (uint32_t)((wm * 32 + mi * 16 + lq + qa_r) * S1 + qa_c);
    #pragma unroll
    for (int p = 0; p < 2; p++)
        bOff[p] = (uint32_t)((wn * 32 + p * 16 + lq + qb_r) * S1 + qb_c);

    float acc[2][4][4];
    #pragma unroll
    for (int mi = 0; mi < 2; mi++)
        #pragma unroll
        for (int ni = 0; ni < 4; ni++)
            #pragma unroll
            for (int q = 0; q < 4; q++) acc[mi][ni][q] = 0.f;

    xp_issue(smc, 0, m0, n0, tid);

    for (int c = 0; c < 8; c++) {
        if (c < 7) {
            xp_issue(smc, c + 1, m0, n0, tid);
            asm volatile("cp.async.wait_group %0;\n" :: "n"(1) : "memory");
        } else {
            asm volatile("cp.async.wait_group %0;\n" :: "n"(0) : "memory");
        }
        __syncthreads();

        char* bufb = smc + (c & 1) * BUFSZ;
        const uint32_t sAh = (uint32_t)__cvta_generic_to_shared(bufb);
        const uint32_t sAl = sAh + PART1;
        const uint32_t sBh = sAl + PART1;
        const uint32_t sBl = sBh + PART1;

        #pragma unroll
        for (int k16 = 0; k16 < 4; k16++) {
            const uint32_t cb = (uint32_t)k16 * 32;
            uint32_t aH[2][4], aL[2][4], bHp[2][4], bLp[2][4];
            #pragma unroll
            for (int mi = 0; mi < 2; mi++) ldsm_x4(aH[mi], sAh + aOff[mi] + cb);
            #pragma unroll
            for (int p = 0; p < 2; p++)   ldsm_x4(bHp[p], sBh + bOff[p] + cb);
            uint32_t bH[4][2], bL[4][2];
            #pragma unroll
            for (int p = 0; p < 2; p++) {
                bH[2 * p][0] = bHp[p][0]; bH[2 * p][1] = bHp[p][1];
                bH[2 * p + 1][0] = bHp[p][2]; bH[2 * p + 1][1] = bHp[p][3];
            }
            #pragma unroll
            for (int mi = 0; mi < 2; mi++)
                #pragma unroll
                for (int ni = 0; ni < 4; ni++) mma_bf16(acc[mi][ni], aH[mi], bH[ni]);
            #pragma unroll
            for (int mi = 0; mi < 2; mi++) ldsm_x4(aL[mi], sAl + aOff[mi] + cb);
            #pragma unroll
            for (int mi = 0; mi < 2; mi++)
                #pragma unroll
                for (int ni = 0; ni < 4; ni++) mma_bf16(acc[mi][ni], aL[mi], bH[ni]);
            #pragma unroll
            for (int p = 0; p < 2; p++)   ldsm_x4(bLp[p], sBl + bOff[p] + cb);
            #pragma unroll
            for (int p = 0; p < 2; p++) {
                bL[2 * p][0] = bLp[p][0]; bL[2 * p][1] = bLp[p][1];
                bL[2 * p + 1][0] = bLp[p][2]; bL[2 * p + 1][1] = bLp[p][3];
            }
            #pragma unroll
            for (int mi = 0; mi < 2; mi++)
                #pragma unroll
                for (int ni = 0; ni < 4; ni++) mma_bf16(acc[mi][ni], aH[mi], bL[ni]);
        }
        __syncthreads();
    }

    // epilogue: D(m, n) -> g_xpT[m][n]
    const int g = lane >> 2, tq = lane & 3;
    #pragma unroll
    for (int mi = 0; mi < 2; mi++) {
        const int m = m0 + wm * 32 + mi * 16 + g;
        #pragma unroll
        for (int ni = 0; ni < 4; ni++) {
            const int n = n0 + wn * 32 + ni * 8 + 2 * tq;
            float2 v01 = make_float2(acc[mi][ni][0], acc[mi][ni][1]);
            float2 v23 = make_float2(acc[mi][ni][2], acc[mi][ni][3]);
            *(float2*)(g_xpT + (size_t)m * TB + n) = v01;
            *(float2*)(g_xpT + (size_t)(m + 8) * TB + n) = v23;
        }
    }
}

// ===========================================================================
// Kernel 2: recurrence. 128 CTAs = 64 col-groups x 2 batch-halves, 256 thr.
// Weights in registers. B fragments via coalesced uint4 loads.
// Register-direct epilogue: activation thread (cc=tid&7, bb=tid>>3) stores ys
// directly; publish pair via shfl_xor(1), one image word per thread.
// Barrier: leader red.release.gpu arrive + ld.acquire.gpu spin (no MEMBAR).
// ===========================================================================
#define OFF_P    0           // 34816 B
#define OFF_BIAS 34816       // 32 floats (128 B)
#define OFF_BASE 34944
#define SMEM2    35072

__global__ void __launch_bounds__(256, 1)
rec_kernel(const float* __restrict__ W_hh, const float* __restrict__ b_ih,
           const float* __restrict__ b_hh, float* __restrict__ ys) {
    extern __shared__ char smc[];
    const int tid = threadIdx.x;
    const int cg = blockIdx.x >> 1, bh = blockIdx.x & 1;
    const int warp = tid >> 5, lane = tid & 31;
    const int g = lane >> 2, tq = lane & 3;

    float* Pb     = (float*)(smc + OFF_P);
    float* bias_s = (float*)(smc + OFF_BIAS);

    unsigned long long* barp = &g_bar2[bh * 16];

    if (tid == 0) {
        unsigned long long v = ld_vol_u64(barp);
        *(unsigned long long*)(smc + OFF_BASE) = (v / BARS_PER_LAUNCH) * BARS_PER_LAUNCH;
    }
    if (tid < 32) {
        const int grow = (tid >> 3) * HID + cg * 8 + (tid & 7);
        bias_s[tid] = __ldg(b_ih + grow) + __ldg(b_hh + grow);
    }

    // ---- preload this lane's weight fragments into registers (once) ----
    const int k0 = warp * 64;
    uint32_t aH[4][2][4], aL[4][2][4];
    #pragma unroll
    for (int kc = 0; kc < 4; kc++) {
        const int k = k0 + kc * 16 + 2 * tq;
        #pragma unroll
        for (int mi = 0; mi < 2; mi++) {
            #pragma unroll
            for (int rr = 0; rr < 2; rr++) {
                const int row = mi * 16 + g + rr * 8;
                const int grow = (row >> 3) * HID + cg * 8 + (row & 7);
                float2 v0 = __ldg((const float2*)(W_hh + (size_t)grow * HID + k));
                float2 v1 = __ldg((const float2*)(W_hh + (size_t)grow * HID + k + 8));
                aH[kc][mi][rr]     = pack_hi2(v0);
                aH[kc][mi][2 + rr] = pack_hi2(v1);
                aL[kc][mi][rr]     = pack_lo2(v0);
                aL[kc][mi][2 + rr] = pack_lo2(v1);
            }
        }
    }
    __syncthreads();
    const unsigned long long base = *(const unsigned long long*)(smc + OFF_BASE);

    // activation identity: one (cc, bb) per thread, ys-coalesced order
    const int cc = tid & 7;      // hidden col within group
    const int bb = tid >> 3;     // batch within half
    float cst = 0.f;

    // publish word for this thread (part = tid parity: even=hi, odd=lo)
    uint32_t pub_word;
    {
        const int part = tid & 1;
        const int cp = cc >> 1;
        const uint32_t blk = (uint32_t)(((cg >> 3) * 4 + ((cg & 7) >> 1)) * 2 + part);
        pub_word = blk * 256u + (uint32_t)(bb >> 4) * 128u
                 + (uint32_t)((bb & 7) * 4 + cp) * 4u
                 + (uint32_t)(2 * ((bb >> 3) & 1) + (cg & 1));
    }

    // prefetch x_proj for t=0
    float xpn[4];
    #pragma unroll
    for (int gate = 0; gate < 4; gate++)
        xpn[gate] = __ldg(g_xpT + (size_t)(gate * HID + cg * 8 + cc) * TB + (size_t)bh * 32 + bb);

    for (int t = 0; t < T_STEPS; t++) {
        float xpc[4];
        #pragma unroll
        for (int gate = 0; gate < 4; gate++) xpc[gate] = xpn[gate];

        if (t > 0) {
            // ---- B fragments: 2x LDG.128 per (kc, part), fully coalesced ----
            const uint32_t* img = g_img[(t - 1) & 1][bh];
            uint32_t bH[4][4][2], bL[4][4][2];
            #pragma unroll
            for (int kc = 0; kc < 4; kc++) {
                const uint32_t blk = (uint32_t)(warp * 4 + kc) * 2;
                uint4 h0 = ldcg_u4(img + blk * 256 + lane * 4);
                uint4 h1 = ldcg_u4(img + blk * 256 + 128 + lane * 4);
                uint4 l0 = ldcg_u4(img + (blk + 1) * 256 + lane * 4);
                uint4 l1 = ldcg_u4(img + (blk + 1) * 256 + 128 + lane * 4);
                bH[kc][0][0] = h0.x; bH[kc][0][1] = h0.y;
                bH[kc][1][0] = h0.z; bH[kc][1][1] = h0.w;
                bH[kc][2][0] = h1.x; bH[kc][2][1] = h1.y;
                bH[kc][3][0] = h1.z; bH[kc][3][1] = h1.w;
                bL[kc][0][0] = l0.x; bL[kc][0][1] = l0.y;
                bL[kc][1][0] = l0.z; bL[kc][1][1] = l0.w;
                bL[kc][2][0] = l1.x; bL[kc][2][1] = l1.y;
                bL[kc][3][0] = l1.z; bL[kc][3][1] = l1.w;
            }

            // ---- pure MMA burst (96 issues, register-resident) ----
            float acc[2][4][4];
            #pragma unroll
            for (int mi = 0; mi < 2; mi++)
                #pragma unroll
                for (int ni = 0; ni < 4; ni++)
                    #pragma unroll
                    for (int q = 0; q < 4; q++) acc[mi][ni][q] = 0.f;

            #pragma unroll
            for (int kc = 0; kc < 4; kc++) {
                #pragma unroll
                for (int mi = 0; mi < 2; mi++)
                    #pragma unroll
                    for (int ni = 0; ni < 4; ni++) mma_bf16(acc[mi][ni], aH[kc][mi], bH[kc][ni]);
                #pragma unroll
                for (int mi = 0; mi < 2; mi++)
                    #pragma unroll
                    for (int ni = 0; ni < 4; ni++) mma_bf16(acc[mi][ni], aL[kc][mi], bH[kc][ni]);
                #pragma unroll
                for (int mi = 0; mi < 2; mi++)
                    #pragma unroll
                    for (int ni = 0; ni < 4; ni++) mma_bf16(acc[mi][ni], aH[kc][mi], bL[kc][ni]);
            }

            // partial stores P[warp][m][n] (n-stride 34, even -> aligned float2)
            #pragma unroll
            for (int mi = 0; mi < 2; mi++) {
                #pragma unroll
                for (int ni = 0; ni < 4; ni++) {
                    const int m = mi * 16 + g;
                    const int n = ni * 8 + 2 * tq;
                    *(float2*)(Pb + (size_t)(warp * 32 + m) * 34 + n) =
                        make_float2(acc[mi][ni][0], acc[mi][ni][1]);
                    *(float2*)(Pb + (size_t)(warp * 32 + m + 8) * 34 + n) =
                        make_float2(acc[mi][ni][2], acc[mi][ni][3]);
                }
            }
        }
        __syncthreads();

        // activations: thread = (cc, bb); h stays in a register
        float h;
        {
            float gv[4];
            #pragma unroll
            for (int gate = 0; gate < 4; gate++) {
                float s = xpc[gate] + bias_s[gate * 8 + cc];
                if (t > 0) {
                    #pragma unroll
                    for (int w = 0; w < 8; w++)
                        s += Pb[(size_t)(w * 32 + gate * 8 + cc) * 34 + bb];
                }
                gv[gate] = s;
            }
            const float ig = fast_sigmoid(gv[0]);
            const float fg = fast_sigmoid(gv[1]);
            const float gg = fast_tanh(gv[2]);
            const float og = fast_sigmoid(gv[3]);
            cst = fg * cst + ig * gg;
            h = og * fast_tanh(cst);
        }

        // publish: pair via shfl_xor(1); even lanes hi word, odd lanes lo word
        if (t < T_STEPS - 1) {
            const float other = __shfl_xor_sync(0xffffffffu, h, 1);
            const int part = tid & 1;
            const float2 hv = part ? make_float2(other, h) : make_float2(h, other);
            const uint32_t w = part ? pack_lo2(hv) : pack_hi2(hv);
            g_img[t & 1][bh][pub_word] = w;
        }

        // ys store: direct from register, warp covers contiguous 32B sectors
        ys[((size_t)t * 64 + bh * 32 + bb) * HID + cg * 8 + cc] = h;

        __syncthreads();   // publish stores done CTA-wide before leader release

        if (t < T_STEPS - 1) {
            // arrive: single release-reduction (no MEMBAR)
            if (tid == 0) red_add_release(barp, 1ull);

            // overlap: next-step x_proj prefetch while peers arrive
            const size_t ncol = (size_t)(t + 1) * 64 + bh * 32 + bb;
            #pragma unroll
            for (int gate = 0; gate < 4; gate++)
                xpn[gate] = __ldg(g_xpT + (size_t)(gate * HID + cg * 8 + cc) * TB + ncol);

            // wait: leader acquire-spins on this half's counter
            if (tid == 0) {
                const unsigned long long tgt =
                    base + (unsigned long long)(t + 1) * GRP_CTAS;
                while (ld_acq_u64(barp) < tgt) { }
            }
            __syncthreads();
        }
    }
}

// ===========================================================================
extern "C" void kernel_launch(void* const* d_in, const int* in_sizes, int n_in,
                              void* d_out, int out_size) {
    (void)in_sizes; (void)n_in; (void)out_size;
    const float* x    = (const float*)d_in[0];
    const float* W_ih = (const float*)d_in[1];
    const float* W_hh = (const float*)d_in[2];
    const float* b_ih = (const float*)d_in[3];
    const float* b_hh = (const float*)d_in[4];
    float* ys = (float*)d_out;

    cudaFuncSetAttribute(xproj_kernel, cudaFuncAttributeMaxDynamicSharedMemorySize, SMEM1);
    cudaFuncSetAttribute(rec_kernel,   cudaFuncAttributeMaxDynamicSharedMemorySize, SMEM2);

    cvt_kernel<<<2048, 256>>>(x, W_ih);
    xproj_kernel<<<4096, 512, SMEM1>>>();
    rec_kernel<<<REC_NCTA, 256, SMEM2>>>(W_hh, b_ih, b_hh, ys);
}

// round 14
// speedup vs baseline: 1.2431x; 1.2431x over previous
#include <cuda_runtime.h>
#include <cuda_bf16.h>
#include <cstdint>
#include <cstddef>

// ---------------------------------------------------------------------------
// LSTM T=512 B=64 I=H=512 on sm_103 (no tcgen05): mma.sync bf16 hi/lo split.
//   cvt2: x -> fragment-ordered bf16 hi/lo images g_ximg[t][bh]
//   rec:  persistent 128-CTA kernel; per step: x-part MMA (W_ih smem + ximg)
//         BEFORE the grid-barrier wait, then h-part MMA (reg weights + h img).
//         Fuses the former xproj kernel into rec's barrier-wait window.
// ---------------------------------------------------------------------------

#define T_STEPS 512
#define BATCH   64
#define HID     512

// fragment-ordered x image: [t][bh][16384 words]
__device__ __align__(16) uint32_t g_ximg[T_STEPS][2][16384];
// fragment-ordered h image: [parity][bh][16384 words]
__device__ __align__(16) uint32_t g_img[2][2][16384];
// per-batch-half barrier counters (128B apart)
__device__ __align__(16) unsigned long long g_bar2[32];

#define REC_NCTA 128
#define GRP_CTAS 64
#define BARS_PER_LAUNCH (511ull * GRP_CTAS)

// ------------------------------ helpers ------------------------------------
__device__ __forceinline__ unsigned long long ld_vol_u64(const unsigned long long* p) {
    unsigned long long v;
    asm volatile("ld.volatile.global.u64 %0, [%1];" : "=l"(v) : "l"(p));
    return v;
}
__device__ __forceinline__ unsigned long long ld_acq_u64(const unsigned long long* p) {
    unsigned long long v;
    asm volatile("ld.acquire.gpu.global.u64 %0, [%1];" : "=l"(v) : "l"(p));
    return v;
}
__device__ __forceinline__ void red_add_release(unsigned long long* p, unsigned long long v) {
    asm volatile("red.release.gpu.global.add.u64 [%0], %1;" :: "l"(p), "l"(v) : "memory");
}
__device__ __forceinline__ uint4 ldcg_u4(const uint32_t* p) {
    uint4 v;
    asm volatile("ld.global.cg.v4.u32 {%0,%1,%2,%3}, [%4];"
                 : "=r"(v.x), "=r"(v.y), "=r"(v.z), "=r"(v.w) : "l"(p));
    return v;
}
__device__ __forceinline__ void ldsm_x4(uint32_t (&r)[4], uint32_t saddr) {
    asm volatile("ldmatrix.sync.aligned.m8n8.x4.shared.b16 {%0,%1,%2,%3}, [%4];"
                 : "=r"(r[0]), "=r"(r[1]), "=r"(r[2]), "=r"(r[3]) : "r"(saddr));
}
__device__ __forceinline__ void mma_bf16(float (&d)[4], const uint32_t (&a)[4],
                                         const uint32_t (&b)[2]) {
    asm volatile(
        "mma.sync.aligned.m16n8k16.row.col.f32.bf16.bf16.f32 "
        "{%0,%1,%2,%3}, {%4,%5,%6,%7}, {%8,%9}, {%0,%1,%2,%3};\n"
        : "+f"(d[0]), "+f"(d[1]), "+f"(d[2]), "+f"(d[3])
        : "r"(a[0]), "r"(a[1]), "r"(a[2]), "r"(a[3]), "r"(b[0]), "r"(b[1]));
}
__device__ __forceinline__ uint32_t pack_hi2(float2 v) {
    union { __nv_bfloat162 h2; uint32_t u; } r;
    r.h2.x = __float2bfloat16(v.x);
    r.h2.y = __float2bfloat16(v.y);
    return r.u;
}
__device__ __forceinline__ uint32_t pack_lo2(float2 v) {
    union { __nv_bfloat162 h2; uint32_t u; } r;
    __nv_bfloat16 hx = __float2bfloat16(v.x);
    __nv_bfloat16 hy = __float2bfloat16(v.y);
    r.h2.x = __float2bfloat16(v.x - __bfloat162float(hx));
    r.h2.y = __float2bfloat16(v.y - __bfloat162float(hy));
    return r.u;
}
__device__ __forceinline__ float fast_sigmoid(float x) { return 1.f / (1.f + __expf(-x)); }
__device__ __forceinline__ float fast_tanh(float x) {
    float ax = fabsf(x);
    float t = 1.f - 2.f / (__expf(2.f * ax) + 1.f);
    return copysignf(t, x);
}

// ===========================================================================
// cvt2: x -> fragment-ordered bf16 hi/lo image per (t, bh).
// Word mapping (matches the h-image consumer exactly):
//   blk = (wk*4+kc)*2 + part ; word = blk*256 + q*128 + lane*4 + j
//   (ni, reg) = (2q + (j>>1), j&1); n = ni*8 + (lane>>2)
//   k = wk*64 + kc*16 + reg*8 + (lane&3)*2  (word holds bf16x2 {k, k+1})
// One thread produces the hi word and the matching lo word (blk+1).
// ===========================================================================
__global__ void cvt2_kernel(const float* __restrict__ x) {
    const size_t gid = (size_t)blockIdx.x * 256 + threadIdx.x;  // 8388608 total
    const int w  = (int)(gid & 8191);
    const int bh = (int)((gid >> 13) & 1);
    const int t  = (int)(gid >> 14);
    const int j = w & 3, lane = (w >> 2) & 31, q = (w >> 7) & 1;
    const int kc = (w >> 8) & 3, wk = w >> 10;
    const int ni = 2 * q + (j >> 1), reg = j & 1;
    const int n = ni * 8 + (lane >> 2);
    const int k = wk * 64 + kc * 16 + reg * 8 + (lane & 3) * 2;
    float2 v = __ldg((const float2*)(x + ((size_t)t * 64 + bh * 32 + n) * 512 + k));
    const uint32_t blk = (uint32_t)(wk * 4 + kc) * 2;
    const uint32_t word = blk * 256u + (uint32_t)q * 128u + (uint32_t)lane * 4u + (uint32_t)j;
    g_ximg[t][bh][word]        = pack_hi2(v);   // part 0 (hi)
    g_ximg[t][bh][word + 256]  = pack_lo2(v);   // part 1 (lo) at blk+1
}

// ===========================================================================
// rec: 128 CTAs = 64 col-groups x 2 batch-halves, 256 thr, persistent.
// Startup: W_hh fragments -> registers; W_ih hi/lo -> SMEM (ldsm layout).
// Per step: x-part MMA first (overlaps peers' h publish), then barrier wait,
// then h-part MMA, combined epilogue, publish h, release.
// SMEM A-tile row stride: 520 elems = 1040 B (65x16B; ldsm conflict-free).
// ===========================================================================
#define SROW    1040
#define OFF_WIHH 0            // 32 rows x 1040 B = 33280
#define OFF_WIHL 33280        // 33280
#define OFF_P    66560        // 8 warps x 32 rows x 34 floats = 34816
#define OFF_BIAS 101376       // 32 floats (128 B)
#define OFF_BASE 101504
#define SMEM2    101632

__global__ void __launch_bounds__(256, 1)
rec_kernel(const float* __restrict__ W_ih, const float* __restrict__ W_hh,
           const float* __restrict__ b_ih, const float* __restrict__ b_hh,
           float* __restrict__ ys) {
    extern __shared__ char smc[];
    const int tid = threadIdx.x;
    const int cg = blockIdx.x >> 1, bh = blockIdx.x & 1;
    const int warp = tid >> 5, lane = tid & 31;
    const int g = lane >> 2, tq = lane & 3;

    float* Pb     = (float*)(smc + OFF_P);
    float* bias_s = (float*)(smc + OFF_BIAS);

    unsigned long long* barp = &g_bar2[bh * 16];

    if (tid == 0) {
        unsigned long long v = ld_vol_u64(barp);
        *(unsigned long long*)(smc + OFF_BASE) = (v / BARS_PER_LAUNCH) * BARS_PER_LAUNCH;
    }
    if (tid < 32) {
        const int grow = (tid >> 3) * HID + cg * 8 + (tid & 7);
        bias_s[tid] = __ldg(b_ih + grow) + __ldg(b_hh + grow);
    }

    // ---- W_ih hi/lo -> SMEM, packed row order (same row map as W_hh regs) ----
    for (int i = tid; i < 32 * 256; i += 256) {     // 8192 float2 loads
        const int r = i >> 8;
        const int kk = (i & 255) * 2;
        const int grow = (r >> 3) * HID + cg * 8 + (r & 7);
        float2 v = __ldg((const float2*)(W_ih + (size_t)grow * HID + kk));
        *(uint32_t*)(smc + OFF_WIHH + r * SROW + kk * 2) = pack_hi2(v);
        *(uint32_t*)(smc + OFF_WIHL + r * SROW + kk * 2) = pack_lo2(v);
    }

    // ---- W_hh fragments -> registers (once) ----
    const int k0 = warp * 64;
    uint32_t aH[4][2][4], aL[4][2][4];
    #pragma unroll
    for (int kc = 0; kc < 4; kc++) {
        const int k = k0 + kc * 16 + 2 * tq;
        #pragma unroll
        for (int mi = 0; mi < 2; mi++) {
            #pragma unroll
            for (int rr = 0; rr < 2; rr++) {
                const int row = mi * 16 + g + rr * 8;
                const int grow = (row >> 3) * HID + cg * 8 + (row & 7);
                float2 v0 = __ldg((const float2*)(W_hh + (size_t)grow * HID + k));
                float2 v1 = __ldg((const float2*)(W_hh + (size_t)grow * HID + k + 8));
                aH[kc][mi][rr]     = pack_hi2(v0);
                aH[kc][mi][2 + rr] = pack_hi2(v1);
                aL[kc][mi][rr]     = pack_lo2(v0);
                aL[kc][mi][2 + rr] = pack_lo2(v1);
            }
        }
    }
    __syncthreads();
    const unsigned long long base = *(const unsigned long long*)(smc + OFF_BASE);

    // ldsm offsets into the W_ih tile for this lane (bytes, incl warp k base)
    const int lq = lane & 7;
    const int qa_r = ((lane >> 3) & 1) * 8;
    const int qa_c = ((lane >> 4) & 1) * 16;
    const uint32_t sWihH = (uint32_t)__cvta_generic_to_shared(smc + OFF_WIHH);
    const uint32_t sWihL = (uint32_t)__cvta_generic_to_shared(smc + OFF_WIHL);
    uint32_t aOffX[2];
    #pragma unroll
    for (int mi = 0; mi < 2; mi++)
        aOffX[mi] = (uint32_t)((mi * 16 + lq + qa_r) * SROW + qa_c + k0 * 2);

    // activation identity: one (cc, bb) per thread, ys-coalesced order
    const int cc = tid & 7;
    const int bb = tid >> 3;
    float cst = 0.f;

    // publish word (part = tid parity: even=hi, odd=lo)
    uint32_t pub_word;
    {
        const int part = tid & 1;
        const int cp = cc >> 1;
        const uint32_t blk = (uint32_t)(((cg >> 3) * 4 + ((cg & 7) >> 1)) * 2 + part);
        pub_word = blk * 256u + (uint32_t)(bb >> 4) * 128u
                 + (uint32_t)((bb & 7) * 4 + cp) * 4u
                 + (uint32_t)(2 * ((bb >> 3) & 1) + (cg & 1));
    }

    for (int t = 0; t < T_STEPS; t++) {
        float acc[2][4][4];
        #pragma unroll
        for (int mi = 0; mi < 2; mi++)
            #pragma unroll
            for (int ni = 0; ni < 4; ni++)
                #pragma unroll
                for (int q = 0; q < 4; q++) acc[mi][ni][q] = 0.f;

        // ================= X phase (no dependency on peers) =================
        {
            const uint32_t* xim = g_ximg[t][bh];
            #pragma unroll
            for (int kc = 0; kc < 4; kc++) {
                const uint32_t blk = (uint32_t)(warp * 4 + kc) * 2;
                uint4 h0 = ldcg_u4(xim + blk * 256 + lane * 4);
                uint4 h1 = ldcg_u4(xim + blk * 256 + 128 + lane * 4);
                uint4 l0 = ldcg_u4(xim + (blk + 1) * 256 + lane * 4);
                uint4 l1 = ldcg_u4(xim + (blk + 1) * 256 + 128 + lane * 4);
                uint32_t xbH[4][2], xbL[4][2];
                xbH[0][0] = h0.x; xbH[0][1] = h0.y;
                xbH[1][0] = h0.z; xbH[1][1] = h0.w;
                xbH[2][0] = h1.x; xbH[2][1] = h1.y;
                xbH[3][0] = h1.z; xbH[3][1] = h1.w;
                xbL[0][0] = l0.x; xbL[0][1] = l0.y;
                xbL[1][0] = l0.z; xbL[1][1] = l0.w;
                xbL[2][0] = l1.x; xbL[2][1] = l1.y;
                xbL[3][0] = l1.z; xbL[3][1] = l1.w;

                uint32_t xaH[2][4], xaL[2][4];
                #pragma unroll
                for (int mi = 0; mi < 2; mi++)
                    ldsm_x4(xaH[mi], sWihH + aOffX[mi] + kc * 32);
                #pragma unroll
                for (int mi = 0; mi < 2; mi++)
                    #pragma unroll
                    for (int ni = 0; ni < 4; ni++) mma_bf16(acc[mi][ni], xaH[mi], xbH[ni]);
                #pragma unroll
                for (int mi = 0; mi < 2; mi++)
                    ldsm_x4(xaL[mi], sWihL + aOffX[mi] + kc * 32);
                #pragma unroll
                for (int mi = 0; mi < 2; mi++)
                    #pragma unroll
                    for (int ni = 0; ni < 4; ni++) mma_bf16(acc[mi][ni], xaL[mi], xbH[ni]);
                #pragma unroll
                for (int mi = 0; mi < 2; mi++)
                    #pragma unroll
                    for (int ni = 0; ni < 4; ni++) mma_bf16(acc[mi][ni], xaH[mi], xbL[ni]);
            }
        }

        // ================= wait for peers' h(t-1), then H phase =============
        if (t > 0) {
            if (tid == 0) {
                const unsigned long long tgt =
                    base + (unsigned long long)t * GRP_CTAS;
                while (ld_acq_u64(barp) < tgt) { }
            }
            __syncthreads();

            const uint32_t* img = g_img[(t - 1) & 1][bh];
            uint32_t bH[4][4][2], bL[4][4][2];
            #pragma unroll
            for (int kc = 0; kc < 4; kc++) {
                const uint32_t blk = (uint32_t)(warp * 4 + kc) * 2;
                uint4 h0 = ldcg_u4(img + blk * 256 + lane * 4);
                uint4 h1 = ldcg_u4(img + blk * 256 + 128 + lane * 4);
                uint4 l0 = ldcg_u4(img + (blk + 1) * 256 + lane * 4);
                uint4 l1 = ldcg_u4(img + (blk + 1) * 256 + 128 + lane * 4);
                bH[kc][0][0] = h0.x; bH[kc][0][1] = h0.y;
                bH[kc][1][0] = h0.z; bH[kc][1][1] = h0.w;
                bH[kc][2][0] = h1.x; bH[kc][2][1] = h1.y;
                bH[kc][3][0] = h1.z; bH[kc][3][1] = h1.w;
                bL[kc][0][0] = l0.x; bL[kc][0][1] = l0.y;
                bL[kc][1][0] = l0.z; bL[kc][1][1] = l0.w;
                bL[kc][2][0] = l1.x; bL[kc][2][1] = l1.y;
                bL[kc][3][0] = l1.z; bL[kc][3][1] = l1.w;
            }
            #pragma unroll
            for (int kc = 0; kc < 4; kc++) {
                #pragma unroll
                for (int mi = 0; mi < 2; mi++)
                    #pragma unroll
                    for (int ni = 0; ni < 4; ni++) mma_bf16(acc[mi][ni], aH[kc][mi], bH[kc][ni]);
                #pragma unroll
                for (int mi = 0; mi < 2; mi++)
                    #pragma unroll
                    for (int ni = 0; ni < 4; ni++) mma_bf16(acc[mi][ni], aL[kc][mi], bH[kc][ni]);
                #pragma unroll
                for (int mi = 0; mi < 2; mi++)
                    #pragma unroll
                    for (int ni = 0; ni < 4; ni++) mma_bf16(acc[mi][ni], aH[kc][mi], bL[kc][ni]);
            }
        }

        // ================= epilogue: partials -> smem -> activation =========
        #pragma unroll
        for (int mi = 0; mi < 2; mi++) {
            #pragma unroll
            for (int ni = 0; ni < 4; ni++) {
                const int m = mi * 16 + g;
                const int n = ni * 8 + 2 * tq;
                *(float2*)(Pb + (size_t)(warp * 32 + m) * 34 + n) =
                    make_float2(acc[mi][ni][0], acc[mi][ni][1]);
                *(float2*)(Pb + (size_t)(warp * 32 + m + 8) * 34 + n) =
                    make_float2(acc[mi][ni][2], acc[mi][ni][3]);
            }
        }
        __syncthreads();

        float h;
        {
            float gv[4];
            #pragma unroll
            for (int gate = 0; gate < 4; gate++) {
                float s = bias_s[gate * 8 + cc];
                #pragma unroll
                for (int w = 0; w < 8; w++)
                    s += Pb[(size_t)(w * 32 + gate * 8 + cc) * 34 + bb];
                gv[gate] = s;
            }
            const float ig = fast_sigmoid(gv[0]);
            const float fg = fast_sigmoid(gv[1]);
            const float gg = fast_tanh(gv[2]);
            const float og = fast_sigmoid(gv[3]);
            cst = fg * cst + ig * gg;
            h = og * fast_tanh(cst);
        }

        // publish: pair via shfl_xor(1); even lanes hi word, odd lanes lo word
        if (t < T_STEPS - 1) {
            const float other = __shfl_xor_sync(0xffffffffu, h, 1);
            const int part = tid & 1;
            const float2 hv = part ? make_float2(other, h) : make_float2(h, other);
            const uint32_t w = part ? pack_lo2(hv) : pack_hi2(hv);
            g_img[t & 1][bh][pub_word] = w;
        }

        // ys store: direct from register
        ys[((size_t)t * 64 + bh * 32 + bb) * HID + cg * 8 + cc] = h;

        __syncthreads();   // publish stores done CTA-wide before leader release

        if (t < T_STEPS - 1 && tid == 0) red_add_release(barp, 1ull);
        // next iteration's X phase overlaps peers' arrival
    }
}

// ===========================================================================
extern "C" void kernel_launch(void* const* d_in, const int* in_sizes, int n_in,
                              void* d_out, int out_size) {
    (void)in_sizes; (void)n_in; (void)out_size;
    const float* x    = (const float*)d_in[0];
    const float* W_ih = (const float*)d_in[1];
    const float* W_hh = (const float*)d_in[2];
    const float* b_ih = (const float*)d_in[3];
    const float* b_hh = (const float*)d_in[4];
    float* ys = (float*)d_out;

    cudaFuncSetAttribute(rec_kernel, cudaFuncAttributeMaxDynamicSharedMemorySize, SMEM2);

    cvt2_kernel<<<32768, 256>>>(x);
    rec_kernel<<<REC_NCTA, 256, SMEM2>>>(W_ih, W_hh, b_ih, b_hh, ys);
}

// round 15
// speedup vs baseline: 1.3776x; 1.1082x over previous
#include <cuda_runtime.h>
#include <cuda_bf16.h>
#include <cstdint>
#include <cstddef>

// ---------------------------------------------------------------------------
// LSTM T=512 B=64 I=H=512 on sm_103 (no tcgen05): mma.sync bf16 hi/lo split.
//   cvt2: x -> fragment-ordered bf16 hi/lo images g_ximg[t][bh]
//   rec:  persistent 128-CTA kernel; X-part MMA before the wait; fine-grained
//         per-(bh, k-group) counters let each WARP wait only for its own 8
//         producer CTAs and start its H-part immediately.
// ---------------------------------------------------------------------------

#define T_STEPS 512
#define BATCH   64
#define HID     512

// fragment-ordered x image: [t][bh][16384 words]
__device__ __align__(16) uint32_t g_ximg[T_STEPS][2][16384];
// fragment-ordered h image: [parity][bh][16384 words]
__device__ __align__(16) uint32_t g_img[2][2][16384];
// fine-grained counters: [bh][k-group], 128B apart. 8 arrivals per step each.
__device__ __align__(16) unsigned long long g_barw[2][8][16];

#define REC_NCTA 128

// ------------------------------ helpers ------------------------------------
__device__ __forceinline__ unsigned long long ld_vol_u64(const unsigned long long* p) {
    unsigned long long v;
    asm volatile("ld.volatile.global.u64 %0, [%1];" : "=l"(v) : "l"(p));
    return v;
}
__device__ __forceinline__ unsigned long long ld_acq_u64(const unsigned long long* p) {
    unsigned long long v;
    asm volatile("ld.acquire.gpu.global.u64 %0, [%1];" : "=l"(v) : "l"(p));
    return v;
}
__device__ __forceinline__ void red_add_release(unsigned long long* p, unsigned long long v) {
    asm volatile("red.release.gpu.global.add.u64 [%0], %1;" :: "l"(p), "l"(v) : "memory");
}
__device__ __forceinline__ uint4 ldcg_u4(const uint32_t* p) {
    uint4 v;
    asm volatile("ld.global.cg.v4.u32 {%0,%1,%2,%3}, [%4];"
                 : "=r"(v.x), "=r"(v.y), "=r"(v.z), "=r"(v.w) : "l"(p));
    return v;
}
__device__ __forceinline__ void ldsm_x4(uint32_t (&r)[4], uint32_t saddr) {
    asm volatile("ldmatrix.sync.aligned.m8n8.x4.shared.b16 {%0,%1,%2,%3}, [%4];"
                 : "=r"(r[0]), "=r"(r[1]), "=r"(r[2]), "=r"(r[3]) : "r"(saddr));
}
__device__ __forceinline__ void mma_bf16(float (&d)[4], const uint32_t (&a)[4],
                                         const uint32_t (&b)[2]) {
    asm volatile(
        "mma.sync.aligned.m16n8k16.row.col.f32.bf16.bf16.f32 "
        "{%0,%1,%2,%3}, {%4,%5,%6,%7}, {%8,%9}, {%0,%1,%2,%3};\n"
        : "+f"(d[0]), "+f"(d[1]), "+f"(d[2]), "+f"(d[3])
        : "r"(a[0]), "r"(a[1]), "r"(a[2]), "r"(a[3]), "r"(b[0]), "r"(b[1]));
}
__device__ __forceinline__ uint32_t pack_hi2(float2 v) {
    union { __nv_bfloat162 h2; uint32_t u; } r;
    r.h2.x = __float2bfloat16(v.x);
    r.h2.y = __float2bfloat16(v.y);
    return r.u;
}
__device__ __forceinline__ uint32_t pack_lo2(float2 v) {
    union { __nv_bfloat162 h2; uint32_t u; } r;
    __nv_bfloat16 hx = __float2bfloat16(v.x);
    __nv_bfloat16 hy = __float2bfloat16(v.y);
    r.h2.x = __float2bfloat16(v.x - __bfloat162float(hx));
    r.h2.y = __float2bfloat16(v.y - __bfloat162float(hy));
    return r.u;
}
__device__ __forceinline__ float fast_sigmoid(float x) { return 1.f / (1.f + __expf(-x)); }
__device__ __forceinline__ float fast_tanh(float x) {
    float ax = fabsf(x);
    float t = 1.f - 2.f / (__expf(2.f * ax) + 1.f);
    return copysignf(t, x);
}

// ===========================================================================
// cvt2: x -> fragment-ordered bf16 hi/lo image per (t, bh).  (proven mapping)
// ===========================================================================
__global__ void cvt2_kernel(const float* __restrict__ x) {
    const size_t gid = (size_t)blockIdx.x * 256 + threadIdx.x;  // 8388608 total
    const int w  = (int)(gid & 8191);
    const int bh = (int)((gid >> 13) & 1);
    const int t  = (int)(gid >> 14);
    const int j = w & 3, lane = (w >> 2) & 31, q = (w >> 7) & 1;
    const int kc = (w >> 8) & 3, wk = w >> 10;
    const int ni = 2 * q + (j >> 1), reg = j & 1;
    const int n = ni * 8 + (lane >> 2);
    const int k = wk * 64 + kc * 16 + reg * 8 + (lane & 3) * 2;
    float2 v = __ldg((const float2*)(x + ((size_t)t * 64 + bh * 32 + n) * 512 + k));
    const uint32_t blk = (uint32_t)(wk * 4 + kc) * 2;
    const uint32_t word = blk * 256u + (uint32_t)q * 128u + (uint32_t)lane * 4u + (uint32_t)j;
    g_ximg[t][bh][word]        = pack_hi2(v);   // part 0 (hi)
    g_ximg[t][bh][word + 256]  = pack_lo2(v);   // part 1 (lo) at blk+1
}

// ===========================================================================
// rec: 128 CTAs = 64 col-groups x 2 batch-halves, 256 thr, persistent.
// Per step: X-part MMA -> per-warp fine-grained wait -> H-part MMA ->
// epilogue reduce -> activation -> publish -> single release to own counter.
// ===========================================================================
#define SROW    1040
#define OFF_WIHH 0            // 32 rows x 1040 B = 33280
#define OFF_WIHL 33280        // 33280
#define OFF_P    66560        // 8 warps x 32 rows x 34 floats = 34816
#define OFF_BIAS 101376       // 32 floats (128 B)
#define SMEM2    101504

__global__ void __launch_bounds__(256, 1)
rec_kernel(const float* __restrict__ W_ih, const float* __restrict__ W_hh,
           const float* __restrict__ b_ih, const float* __restrict__ b_hh,
           float* __restrict__ ys) {
    extern __shared__ char smc[];
    const int tid = threadIdx.x;
    const int cg = blockIdx.x >> 1, bh = blockIdx.x & 1;
    const int warp = tid >> 5, lane = tid & 31;
    const int g = lane >> 2, tq = lane & 3;

    float* Pb     = (float*)(smc + OFF_P);
    float* bias_s = (float*)(smc + OFF_BIAS);

    // per-warp consumer counter + replay-safe base (read before any arrival)
    const unsigned long long* wcnt = &g_barw[bh][warp][0];
    const unsigned long long wbase = ld_vol_u64(wcnt);
    // producer counter for this CTA's k-group
    unsigned long long* pcnt = &g_barw[bh][cg >> 3][0];

    if (tid < 32) {
        const int grow = (tid >> 3) * HID + cg * 8 + (tid & 7);
        bias_s[tid] = __ldg(b_ih + grow) + __ldg(b_hh + grow);
    }

    // ---- W_ih hi/lo -> SMEM, packed row order ----
    for (int i = tid; i < 32 * 256; i += 256) {
        const int r = i >> 8;
        const int kk = (i & 255) * 2;
        const int grow = (r >> 3) * HID + cg * 8 + (r & 7);
        float2 v = __ldg((const float2*)(W_ih + (size_t)grow * HID + kk));
        *(uint32_t*)(smc + OFF_WIHH + r * SROW + kk * 2) = pack_hi2(v);
        *(uint32_t*)(smc + OFF_WIHL + r * SROW + kk * 2) = pack_lo2(v);
    }

    // ---- W_hh fragments -> registers (once) ----
    const int k0 = warp * 64;
    uint32_t aH[4][2][4], aL[4][2][4];
    #pragma unroll
    for (int kc = 0; kc < 4; kc++) {
        const int k = k0 + kc * 16 + 2 * tq;
        #pragma unroll
        for (int mi = 0; mi < 2; mi++) {
            #pragma unroll
            for (int rr = 0; rr < 2; rr++) {
                const int row = mi * 16 + g + rr * 8;
                const int grow = (row >> 3) * HID + cg * 8 + (row & 7);
                float2 v0 = __ldg((const float2*)(W_hh + (size_t)grow * HID + k));
                float2 v1 = __ldg((const float2*)(W_hh + (size_t)grow * HID + k + 8));
                aH[kc][mi][rr]     = pack_hi2(v0);
                aH[kc][mi][2 + rr] = pack_hi2(v1);
                aL[kc][mi][rr]     = pack_lo2(v0);
                aL[kc][mi][2 + rr] = pack_lo2(v1);
            }
        }
    }
    __syncthreads();

    // ldsm offsets into the W_ih tile (bytes, incl warp k base)
    const int lq = lane & 7;
    const int qa_r = ((lane >> 3) & 1) * 8;
    const int qa_c = ((lane >> 4) & 1) * 16;
    const uint32_t sWihH = (uint32_t)__cvta_generic_to_shared(smc + OFF_WIHH);
    const uint32_t sWihL = (uint32_t)__cvta_generic_to_shared(smc + OFF_WIHL);
    uint32_t aOffX[2];
    #pragma unroll
    for (int mi = 0; mi < 2; mi++)
        aOffX[mi] = (uint32_t)((mi * 16 + lq + qa_r) * SROW + qa_c + k0 * 2);

    // activation identity: one (cc, bb) per thread, ys-coalesced order
    const int cc = tid & 7;
    const int bb = tid >> 3;
    float cst = 0.f;

    // publish word (part = tid parity: even=hi, odd=lo)
    uint32_t pub_word;
    {
        const int part = tid & 1;
        const int cp = cc >> 1;
        const uint32_t blk = (uint32_t)(((cg >> 3) * 4 + ((cg & 7) >> 1)) * 2 + part);
        pub_word = blk * 256u + (uint32_t)(bb >> 4) * 128u
                 + (uint32_t)((bb & 7) * 4 + cp) * 4u
                 + (uint32_t)(2 * ((bb >> 3) & 1) + (cg & 1));
    }

    for (int t = 0; t < T_STEPS; t++) {
        float acc[2][4][4];
        #pragma unroll
        for (int mi = 0; mi < 2; mi++)
            #pragma unroll
            for (int ni = 0; ni < 4; ni++)
                #pragma unroll
                for (int q = 0; q < 4; q++) acc[mi][ni][q] = 0.f;

        // ================= X phase (no dependency on peers) =================
        {
            const uint32_t* xim = g_ximg[t][bh];
            #pragma unroll
            for (int kc = 0; kc < 4; kc++) {
                const uint32_t blk = (uint32_t)(warp * 4 + kc) * 2;
                uint4 h0 = ldcg_u4(xim + blk * 256 + lane * 4);
                uint4 h1 = ldcg_u4(xim + blk * 256 + 128 + lane * 4);
                uint4 l0 = ldcg_u4(xim + (blk + 1) * 256 + lane * 4);
                uint4 l1 = ldcg_u4(xim + (blk + 1) * 256 + 128 + lane * 4);
                uint32_t xbH[4][2], xbL[4][2];
                xbH[0][0] = h0.x; xbH[0][1] = h0.y;
                xbH[1][0] = h0.z; xbH[1][1] = h0.w;
                xbH[2][0] = h1.x; xbH[2][1] = h1.y;
                xbH[3][0] = h1.z; xbH[3][1] = h1.w;
                xbL[0][0] = l0.x; xbL[0][1] = l0.y;
                xbL[1][0] = l0.z; xbL[1][1] = l0.w;
                xbL[2][0] = l1.x; xbL[2][1] = l1.y;
                xbL[3][0] = l1.z; xbL[3][1] = l1.w;

                uint32_t xaH[2][4], xaL[2][4];
                #pragma unroll
                for (int mi = 0; mi < 2; mi++)
                    ldsm_x4(xaH[mi], sWihH + aOffX[mi] + kc * 32);
                #pragma unroll
                for (int mi = 0; mi < 2; mi++)
                    #pragma unroll
                    for (int ni = 0; ni < 4; ni++) mma_bf16(acc[mi][ni], xaH[mi], xbH[ni]);
                #pragma unroll
                for (int mi = 0; mi < 2; mi++)
                    ldsm_x4(xaL[mi], sWihL + aOffX[mi] + kc * 32);
                #pragma unroll
                for (int mi = 0; mi < 2; mi++)
                    #pragma unroll
                    for (int ni = 0; ni < 4; ni++) mma_bf16(acc[mi][ni], xaL[mi], xbH[ni]);
                #pragma unroll
                for (int mi = 0; mi < 2; mi++)
                    #pragma unroll
                    for (int ni = 0; ni < 4; ni++) mma_bf16(acc[mi][ni], xaH[mi], xbL[ni]);
            }
        }

        // ===== per-warp wait for THIS warp's 8 producers, then H phase ======
        if (t > 0) {
            const unsigned long long tgt = wbase + (unsigned long long)t * 8ull;
            while (ld_acq_u64(wcnt) < tgt) { }   // all lanes spin (1 req/warp)

            const uint32_t* img = g_img[(t - 1) & 1][bh];
            uint32_t bH[4][4][2], bL[4][4][2];
            #pragma unroll
            for (int kc = 0; kc < 4; kc++) {
                const uint32_t blk = (uint32_t)(warp * 4 + kc) * 2;
                uint4 h0 = ldcg_u4(img + blk * 256 + lane * 4);
                uint4 h1 = ldcg_u4(img + blk * 256 + 128 + lane * 4);
                uint4 l0 = ldcg_u4(img + (blk + 1) * 256 + lane * 4);
                uint4 l1 = ldcg_u4(img + (blk + 1) * 256 + 128 + lane * 4);
                bH[kc][0][0] = h0.x; bH[kc][0][1] = h0.y;
                bH[kc][1][0] = h0.z; bH[kc][1][1] = h0.w;
                bH[kc][2][0] = h1.x; bH[kc][2][1] = h1.y;
                bH[kc][3][0] = h1.z; bH[kc][3][1] = h1.w;
                bL[kc][0][0] = l0.x; bL[kc][0][1] = l0.y;
                bL[kc][1][0] = l0.z; bL[kc][1][1] = l0.w;
                bL[kc][2][0] = l1.x; bL[kc][2][1] = l1.y;
                bL[kc][3][0] = l1.z; bL[kc][3][1] = l1.w;
            }
            #pragma unroll
            for (int kc = 0; kc < 4; kc++) {
                #pragma unroll
                for (int mi = 0; mi < 2; mi++)
                    #pragma unroll
                    for (int ni = 0; ni < 4; ni++) mma_bf16(acc[mi][ni], aH[kc][mi], bH[kc][ni]);
                #pragma unroll
                for (int mi = 0; mi < 2; mi++)
                    #pragma unroll
                    for (int ni = 0; ni < 4; ni++) mma_bf16(acc[mi][ni], aL[kc][mi], bH[kc][ni]);
                #pragma unroll
                for (int mi = 0; mi < 2; mi++)
                    #pragma unroll
                    for (int ni = 0; ni < 4; ni++) mma_bf16(acc[mi][ni], aH[kc][mi], bL[kc][ni]);
            }
        }

        // ================= epilogue: partials -> smem -> activation =========
        #pragma unroll
        for (int mi = 0; mi < 2; mi++) {
            #pragma unroll
            for (int ni = 0; ni < 4; ni++) {
                const int m = mi * 16 + g;
                const int n = ni * 8 + 2 * tq;
                *(float2*)(Pb + (size_t)(warp * 32 + m) * 34 + n) =
                    make_float2(acc[mi][ni][0], acc[mi][ni][1]);
                *(float2*)(Pb + (size_t)(warp * 32 + m + 8) * 34 + n) =
                    make_float2(acc[mi][ni][2], acc[mi][ni][3]);
            }
        }
        __syncthreads();

        float h;
        {
            float gv[4];
            #pragma unroll
            for (int gate = 0; gate < 4; gate++) {
                float s = bias_s[gate * 8 + cc];
                #pragma unroll
                for (int w = 0; w < 8; w++)
                    s += Pb[(size_t)(w * 32 + gate * 8 + cc) * 34 + bb];
                gv[gate] = s;
            }
            const float ig = fast_sigmoid(gv[0]);
            const float fg = fast_sigmoid(gv[1]);
            const float gg = fast_tanh(gv[2]);
            const float og = fast_sigmoid(gv[3]);
            cst = fg * cst + ig * gg;
            h = og * fast_tanh(cst);
        }

        // publish: pair via shfl_xor(1); even lanes hi word, odd lanes lo word
        if (t < T_STEPS - 1) {
            const float other = __shfl_xor_sync(0xffffffffu, h, 1);
            const int part = tid & 1;
            const float2 hv = part ? make_float2(other, h) : make_float2(h, other);
            const uint32_t w = part ? pack_lo2(hv) : pack_hi2(hv);
            g_img[t & 1][bh][pub_word] = w;
        }

        // ys store: direct from register
        ys[((size_t)t * 64 + bh * 32 + bb) * HID + cg * 8 + cc] = h;

        __syncthreads();   // publish stores done CTA-wide before release

        if (t < T_STEPS - 1 && tid == 0) red_add_release(pcnt, 1ull);
        // next iteration's X phase overlaps peers' arrival
    }
}

// ===========================================================================
extern "C" void kernel_launch(void* const* d_in, const int* in_sizes, int n_in,
                              void* d_out, int out_size) {
    (void)in_sizes; (void)n_in; (void)out_size;
    const float* x    = (const float*)d_in[0];
    const float* W_ih = (const float*)d_in[1];
    const float* W_hh = (const float*)d_in[2];
    const float* b_ih = (const float*)d_in[3];
    const float* b_hh = (const float*)d_in[4];
    float* ys = (float*)d_out;

    cudaFuncSetAttribute(rec_kernel, cudaFuncAttributeMaxDynamicSharedMemorySize, SMEM2);

    cvt2_kernel<<<32768, 256>>>(x);
    rec_kernel<<<REC_NCTA, 256, SMEM2>>>(W_ih, W_hh, b_ih, b_hh, ys);
}